// round 5
// baseline (speedup 1.0000x reference)
#include <cuda_runtime.h>
#include <cuda_bf16.h>
#include <cstdint>

// Problem shape (fixed by the dataset)
#define BB   32
#define TT   1000
#define VV   1024
#define LL   128
#define SS   (2*LL + 1)      // 257 extended lattice states
#define LPP  132             // padded lp row: slots 0..127 = labels y1..yL, 128 = blank
#define NEGF (-1e30f)
#define L2E  1.4426950408889634f   // log2(e)
#define LN2  0.6931471805599453f   // ln(2)

// Scratch (no cudaMalloc allowed)
__device__ __align__(16) float g_lp2[(size_t)BB * TT * LPP];  // ~16.9 MB, L2-resident
__device__ float g_part[BB];

// ---------------------------------------------------------------------------
// log2-domain logaddexp via 1 MUFU (EX2) + FMA polynomial for log2(1+y).
// y = 2^-|x-z| in (0,1]; split at sqrt(2)-1 so t in (-0.293, 0.414],
// degree-6 Taylor of log2(1+t): |err| <= 4.3e-4 (log2 units) per call.
// Exact when one input is NEGF (y==0 -> returns max).
// ---------------------------------------------------------------------------
__device__ __forceinline__ float ladd2(float x, float z) {
    float m = fmaxf(x, z);
    float d = fminf(x, z) - m;             // -|x-z|  (0 if equal, even at NEG)
    float e = exp2f(d);                    // (0,1]
    bool  big = e > 0.41421356f;
    float t  = big ? fmaf(e, 0.5f, -0.5f) : e;
    float p  =       -0.24044917f;
    p = fmaf(p, t,    0.28853901f);
    p = fmaf(p, t,   -0.36067376f);
    p = fmaf(p, t,    0.48089835f);
    p = fmaf(p, t,   -0.72134752f);
    p = fmaf(p, t,    1.44269504f);
    float l = p * t;
    return (m + (big ? 1.0f : 0.0f)) + l;
}

// ---------------------------------------------------------------------------
// Kernel 1: per (b,t) one-pass online log-sum-exp over V (base-2) + gather.
// 256 threads, one float4 per thread. Gather re-reads the (cache-hot) row.
// ---------------------------------------------------------------------------
__global__ __launch_bounds__(256) void k_lse_gather(
    const float* __restrict__ hs, const int* __restrict__ ys)
{
    const int bt  = blockIdx.x;            // = b*TT + t
    const int b   = bt / TT;
    const int tid = threadIdx.x;
    const int wid = tid >> 5, lane = tid & 31;

    const float* __restrict__ row = hs + (size_t)bt * VV;
    float4 v = reinterpret_cast<const float4*>(row)[tid];
    v.x *= L2E; v.y *= L2E; v.z *= L2E; v.w *= L2E;

    float m = fmaxf(fmaxf(v.x, v.y), fmaxf(v.z, v.w));
    float s = exp2f(v.x - m) + exp2f(v.y - m) + exp2f(v.z - m) + exp2f(v.w - m);

    // warp-level (m,s) reduction
    #pragma unroll
    for (int o = 16; o > 0; o >>= 1) {
        float om = __shfl_xor_sync(0xffffffffu, m, o);
        float os = __shfl_xor_sync(0xffffffffu, s, o);
        float M  = fmaxf(m, om);
        s = fmaf(os, exp2f(om - M), s * exp2f(m - M));
        m = M;
    }

    __shared__ float wm[8], ws[8];
    __shared__ float sh_lse;
    if (lane == 0) { wm[wid] = m; ws[wid] = s; }
    __syncthreads();
    if (tid == 0) {
        float M = wm[0];
        #pragma unroll
        for (int i = 1; i < 8; i++) M = fmaxf(M, wm[i]);
        float S = 0.0f;
        #pragma unroll
        for (int i = 0; i < 8; i++) S += ws[i] * exp2f(wm[i] - M);
        sh_lse = M + log2f(S);
    }
    __syncthreads();
    const float lse2 = sh_lse;

    // Gather: slots 0..127 = labels y1..yL, slot 128 = blank (vocab 0)
    if (tid < LL + 1) {
        int idx = (tid < LL) ? ys[b * LL + tid] : 0;
        g_lp2[(size_t)bt * LPP + tid] = row[idx] * L2E - lse2;
    }
}

// ---------------------------------------------------------------------------
// Kernel 2: CTC forward DP. ONE WARP per batch element, alpha in registers.
// Thread `lane` owns states s = 8*lane + j (j=0..7); lane 31 also owns s=256.
// j parity == state parity for every lane -> uniform blank/label code paths.
// Per step: 1 shfl_up (boundary), 1 LDG.128 + 1 broadcast LDG.32 (prefetched
// one step ahead), 13 ladd2 calls. No barriers, no shared memory in the loop.
// ---------------------------------------------------------------------------
__global__ __launch_bounds__(32) void k_ctc_dp(
    const int* __restrict__ hlens, const int* __restrict__ ys,
    const int* __restrict__ ylens)
{
    const int b    = blockIdx.x;
    const int lane = threadIdx.x;
    const float* __restrict__ base = g_lp2 + (size_t)b * TT * LPP;
    const int*   __restrict__ yrow = ys + b * LL;

    const int k0 = 4 * lane;               // label index for j=1; j=3,5,7 -> k0+1..3
    int ym1 = (lane == 0) ? -1 : yrow[k0 - 1];
    int y0 = yrow[k0], y1 = yrow[k0 + 1], y2 = yrow[k0 + 2], y3 = yrow[k0 + 3];
    const bool sk0 = (lane != 0) && (y0 != ym1);   // state 8l+1 (s=1 never skips)
    const bool sk1 = (y1 != y0);
    const bool sk2 = (y2 != y1);
    const bool sk3 = (y3 != y2);

    float a0 = NEGF, a1 = NEGF, a2 = NEGF, a3 = NEGF;
    float a4 = NEGF, a5 = NEGF, a6 = NEGF, a7 = NEGF;
    float a256 = NEGF;                     // meaningful only on lane 31

    if (lane == 0) {                       // t=0: states 0 (blank) and 1 (label 1)
        a0 = base[128];
        a1 = base[0];
    }

    const int hlen = hlens[b];
    int tmax = hlen - 1; if (tmax > TT - 1) tmax = TT - 1;

    float4 cur4 = make_float4(0.f, 0.f, 0.f, 0.f);
    float  curb = 0.f;
    if (tmax >= 1) {
        cur4 = *reinterpret_cast<const float4*>(base + LPP + k0);
        curb = base[LPP + 128];
    }
    const float* p = base + 2 * (size_t)LPP;

    for (int t = 1; t <= tmax; ++t) {
        // prefetch next row (clamped pointer avoids a branch on the last iter)
        const float* pp = (t < tmax) ? p : base;
        float4 nx4 = *reinterpret_cast<const float4*>(pp + k0);
        float  nxb = pp[128];

        // boundary: old alpha[8*lane - 1] = neighbor's old a7
        float n1 = __shfl_up_sync(0xffffffffu, a7, 1);
        if (lane == 0) n1 = NEGF;

        // s = 256 (blank) — uses OLD a7 (s=255); junk on lanes != 31, never read
        a256 = ladd2(a256, a7) + curb;

        // descending j keeps all reads on old values
        { float r = ladd2(a7, a6); r = ladd2(r, sk3 ? a5 : NEGF); a7 = r + cur4.w; }
        a6 = ladd2(a6, a5) + curb;
        { float r = ladd2(a5, a4); r = ladd2(r, sk2 ? a3 : NEGF); a5 = r + cur4.z; }
        a4 = ladd2(a4, a3) + curb;
        { float r = ladd2(a3, a2); r = ladd2(r, sk1 ? a1 : NEGF); a3 = r + cur4.y; }
        a2 = ladd2(a2, a1) + curb;
        { float r = ladd2(a1, a0); r = ladd2(r, sk0 ? n1 : NEGF); a1 = r + cur4.x; }
        a0 = ladd2(a0, n1) + curb;

        cur4 = nx4; curb = nxb; p += LPP;
    }

    // final readout
    __shared__ float fin[SS];
    fin[8 * lane + 0] = a0; fin[8 * lane + 1] = a1;
    fin[8 * lane + 2] = a2; fin[8 * lane + 3] = a3;
    fin[8 * lane + 4] = a4; fin[8 * lane + 5] = a5;
    fin[8 * lane + 6] = a6; fin[8 * lane + 7] = a7;
    if (lane == 31) fin[256] = a256;
    __syncwarp();
    if (lane == 0) {
        int yl = ylens[b];
        float la2 = ladd2(fin[2 * yl], fin[2 * yl - 1]);
        g_part[b] = -(la2 * LN2) / (float)yl;
    }
}

// ---------------------------------------------------------------------------
// Kernel 3: mean over batch.
// ---------------------------------------------------------------------------
__global__ void k_finish(float* __restrict__ out)
{
    int tid = threadIdx.x;
    float v = (tid < BB) ? g_part[tid] : 0.0f;
    #pragma unroll
    for (int o = 16; o > 0; o >>= 1)
        v += __shfl_xor_sync(0xffffffffu, v, o);
    if (tid == 0) out[0] = v / (float)BB;
}

extern "C" void kernel_launch(void* const* d_in, const int* in_sizes, int n_in,
                              void* d_out, int out_size)
{
    (void)in_sizes; (void)n_in; (void)out_size;
    const float* hs    = (const float*)d_in[0];
    const int*   hlens = (const int*)  d_in[1];
    const int*   ys    = (const int*)  d_in[2];
    const int*   ylens = (const int*)  d_in[3];
    float*       out   = (float*)d_out;

    k_lse_gather<<<BB * TT, 256>>>(hs, ys);
    k_ctc_dp<<<BB, 32>>>(hlens, ys, ylens);
    k_finish<<<1, 32>>>(out);
}

// round 6
// speedup vs baseline: 1.4919x; 1.4919x over previous
#include <cuda_runtime.h>
#include <cuda_bf16.h>
#include <cstdint>

// Problem shape (fixed by the dataset)
#define BB   32
#define TT   1000
#define VV   1024
#define LL   128
#define SS   (2*LL + 1)      // 257 extended lattice states
#define LPP  132             // padded lp row: slots 0..127 = labels, 128 = blank
#define NEGF (-1e30f)
#define L2E  1.4426950408889634f   // log2(e)
#define LN2  0.6931471805599453f   // ln(2)

// Scratch (no cudaMalloc allowed)
__device__ __align__(16) float g_lp2[(size_t)BB * TT * LPP];  // ~16.9 MB, L2-resident
__device__ float g_part[BB];

// MUFU wrappers (guarantee single EX2/LG2 regardless of fast-math flags)
__device__ __forceinline__ float ex2_(float x) {
    float r; asm("ex2.approx.ftz.f32 %0, %1;" : "=f"(r) : "f"(x)); return r;
}
__device__ __forceinline__ float lg2_(float x) {
    float r; asm("lg2.approx.ftz.f32 %0, %1;" : "=f"(r) : "f"(x)); return r;
}

// log2-domain logaddexp, 2-way and 3-way (hardware MUFU, no polynomial)
__device__ __forceinline__ float lse2(float a, float b) {
    float m = fmaxf(a, b);
    float e = ex2_(a - m) + ex2_(b - m);
    return m + lg2_(e);
}
__device__ __forceinline__ float lse3(float a, float b, float c) {
    float m = fmaxf(fmaxf(a, b), c);
    float e = ex2_(a - m) + ex2_(b - m) + ex2_(c - m);
    return m + lg2_(e);
}

// ---------------------------------------------------------------------------
// Kernel 1: ONE WARP per (b,t) row. 8 float4 per lane, warp-only (m,s)
// reduction, no shared memory, no block barriers. Gather re-reads the hot row.
// ---------------------------------------------------------------------------
__global__ __launch_bounds__(256) void k_lse_gather(
    const float* __restrict__ hs, const int* __restrict__ ys)
{
    const int wid  = threadIdx.x >> 5, lane = threadIdx.x & 31;
    const int rowi = blockIdx.x * 8 + wid;          // b*TT + t
    const int b    = rowi / TT;

    const float*  __restrict__ row = hs + (size_t)rowi * VV;
    const float4* __restrict__ r4  = reinterpret_cast<const float4*>(row);

    float4 v[8];
    #pragma unroll
    for (int i = 0; i < 8; i++) v[i] = r4[i * 32 + lane];

    float m = NEGF;
    #pragma unroll
    for (int i = 0; i < 8; i++)
        m = fmaxf(m, fmaxf(fmaxf(v[i].x, v[i].y), fmaxf(v[i].z, v[i].w)));
    #pragma unroll
    for (int o = 16; o > 0; o >>= 1)
        m = fmaxf(m, __shfl_xor_sync(0xffffffffu, m, o));

    const float mL2 = m * L2E;                       // work in base-2
    float s = 0.0f;
    #pragma unroll
    for (int i = 0; i < 8; i++) {
        s += ex2_(fmaf(v[i].x, L2E, -mL2));
        s += ex2_(fmaf(v[i].y, L2E, -mL2));
        s += ex2_(fmaf(v[i].z, L2E, -mL2));
        s += ex2_(fmaf(v[i].w, L2E, -mL2));
    }
    #pragma unroll
    for (int o = 16; o > 0; o >>= 1)
        s += __shfl_xor_sync(0xffffffffu, s, o);

    const float lse = mL2 + lg2_(s);                 // log2(sum exp(x))

    // Gather: slots 0..127 = labels y1..yL, slot 128 = blank (vocab 0)
    const int* __restrict__ yrow = ys + b * LL;
    float* __restrict__ dst = g_lp2 + (size_t)rowi * LPP;
    #pragma unroll
    for (int j = lane; j <= LL; j += 32) {
        int idx = (j < LL) ? yrow[j] : 0;
        dst[j] = fmaf(row[idx], L2E, -lse);
    }
}

// ---------------------------------------------------------------------------
// Kernel 2: CTC forward DP. One block of 128 threads per batch element.
// Thread k owns blank state 2k (a0) and label state 2k+1 (a1); thread 127
// also owns final blank state 256 (ax). Per step each thread needs exactly
// one neighbor value: old a1[k-1] -> 1 shfl_up + double-buffered 4-float
// smem handoff at warp boundaries + ONE __syncthreads per step.
// ---------------------------------------------------------------------------
__global__ __launch_bounds__(128) void k_ctc_dp(
    const int* __restrict__ hlens, const int* __restrict__ ys,
    const int* __restrict__ ylens)
{
    const int b    = blockIdx.x;
    const int tid  = threadIdx.x;
    const int lane = tid & 31, wid = tid >> 5;

    const float* __restrict__ base = g_lp2 + (size_t)b * TT * LPP;
    const int*   __restrict__ yrow = ys + b * LL;

    const bool skip = (tid > 0) && (yrow[tid] != yrow[tid - 1]);

    float a0 = NEGF, a1 = NEGF, ax = NEGF;
    if (tid == 0) { a0 = base[128]; a1 = base[0]; }   // t=0 init

    const int hlen = hlens[b];
    int tmax = hlen - 1; if (tmax > TT - 1) tmax = TT - 1;

    __shared__ float sb[2][4];
    __shared__ float fin[SS];

    // prefetched lp for step t=1
    float lpl = 0.0f, lpb = 0.0f;
    if (tmax >= 1) { lpl = base[LPP + tid]; lpb = base[LPP + 128]; }
    const float* p = base + 2 * (size_t)LPP;
    int pb = 0;

    for (int t = 1; t <= tmax; ++t) {
        // prefetch next row (clamped pointer, no extra branch cost)
        const float* pp = (t < tmax) ? p : base;
        float nlpl = pp[tid];
        float nlpb = pp[128];

        if (lane == 31) sb[pb][wid] = a1;
        __syncthreads();
        float n = __shfl_up_sync(0xffffffffu, a1, 1);
        if (lane == 0) n = wid ? sb[pb][wid - 1] : NEGF;

        float na0 = lse2(a0, n) + lpb;                     // blank 2k
        float na1 = lse3(a1, a0, skip ? n : NEGF) + lpl;   // label 2k+1
        if (tid == 127) ax = lse2(ax, a1) + lpb;           // blank 256

        a0 = na0; a1 = na1;
        lpl = nlpl; lpb = nlpb; p += LPP; pb ^= 1;
    }

    fin[2 * tid]     = a0;
    fin[2 * tid + 1] = a1;
    if (tid == 127) fin[256] = ax;
    __syncthreads();
    if (tid == 0) {
        int yl = ylens[b];
        float la2 = lse2(fin[2 * yl], fin[2 * yl - 1]);
        g_part[b] = -(la2 * LN2) / (float)yl;
    }
}

// ---------------------------------------------------------------------------
// Kernel 3: mean over batch.
// ---------------------------------------------------------------------------
__global__ void k_finish(float* __restrict__ out)
{
    int tid = threadIdx.x;
    float v = (tid < BB) ? g_part[tid] : 0.0f;
    #pragma unroll
    for (int o = 16; o > 0; o >>= 1)
        v += __shfl_xor_sync(0xffffffffu, v, o);
    if (tid == 0) out[0] = v / (float)BB;
}

extern "C" void kernel_launch(void* const* d_in, const int* in_sizes, int n_in,
                              void* d_out, int out_size)
{
    (void)in_sizes; (void)n_in; (void)out_size;
    const float* hs    = (const float*)d_in[0];
    const int*   hlens = (const int*)  d_in[1];
    const int*   ys    = (const int*)  d_in[2];
    const int*   ylens = (const int*)  d_in[3];
    float*       out   = (float*)d_out;

    k_lse_gather<<<(BB * TT) / 8, 256>>>(hs, ys);
    k_ctc_dp<<<BB, 128>>>(hlens, ys, ylens);
    k_finish<<<1, 32>>>(out);
}